// round 4
// baseline (speedup 1.0000x reference)
#include <cuda_runtime.h>
#include <math.h>

// x[1, 2M, 16] fp32, ~5% NaN. Per-column mean of valid entries; NaNs -> mean.
//
// Single persistent kernel:
//   phase1: stream tile once: copy raw x -> out, accumulate per-column
//           sum, record NaN positions in per-lane 64-bit register bitmasks.
//   grid barrier
//   phase2: predicated 4B scatter stores of column mean to NaN lanes only.
// No second full read of the input.

#define C 16
#define THREADS 256

struct Acc {
    float sum[C];
    float cnt[C];
    unsigned int counter;
};
__device__ Acc g_acc;

__global__ void __launch_bounds__(THREADS)
fused_kernel(const float4* __restrict__ in, float4* __restrict__ out,
             long long n4, long long chunk) {
    __shared__ float s_sum[C];
    __shared__ float s_cnt[C];
    __shared__ float s_mean[C];

    const int t = threadIdx.x;
    if (t < C) { s_sum[t] = 0.0f; s_cnt[t] = 0.0f; }
    __syncthreads();

    const long long base  = (long long)blockIdx.x * chunk;
    const long long end   = (base + chunk < n4) ? (base + chunk) : n4;
    const long long start = base + t;

    // Column group is invariant across the strided loop.
    const int cg    = (int)(start & 3);
    const int cbase = cg * 4;

    float ls0 = 0.f, ls1 = 0.f, ls2 = 0.f, ls3 = 0.f;
    unsigned long long m0 = 0ull, m1 = 0ull, m2 = 0ull, m3 = 0ull;
    int iters = 0;

    // ---------- phase 1: single streaming pass ----------
    #pragma unroll 4
    for (long long i = start; i < end; i += THREADS) {
        float4 v = in[i];
        bool n0 = !(v.x == v.x);
        bool n1 = !(v.y == v.y);
        bool n2 = !(v.z == v.z);
        bool n3 = !(v.w == v.w);
        ls0 += n0 ? 0.0f : v.x;
        ls1 += n1 ? 0.0f : v.y;
        ls2 += n2 ? 0.0f : v.z;
        ls3 += n3 ? 0.0f : v.w;
        unsigned long long bit = 1ull << iters;
        if (n0) m0 |= bit;
        if (n1) m1 |= bit;
        if (n2) m2 |= bit;
        if (n3) m3 |= bit;
        out[i] = v;            // raw copy-through (NaNs fixed in phase 2)
        iters++;
    }

    float fi = (float)iters;
    atomicAdd(&s_sum[cbase + 0], ls0);
    atomicAdd(&s_sum[cbase + 1], ls1);
    atomicAdd(&s_sum[cbase + 2], ls2);
    atomicAdd(&s_sum[cbase + 3], ls3);
    atomicAdd(&s_cnt[cbase + 0], fi - (float)__popcll(m0));
    atomicAdd(&s_cnt[cbase + 1], fi - (float)__popcll(m1));
    atomicAdd(&s_cnt[cbase + 2], fi - (float)__popcll(m2));
    atomicAdd(&s_cnt[cbase + 3], fi - (float)__popcll(m3));
    __syncthreads();

    if (t < C) {
        atomicAdd(&g_acc.sum[t], s_sum[t]);
        atomicAdd(&g_acc.cnt[t], s_cnt[t]);
        __threadfence();
    }
    __syncthreads();

    // ---------- grid barrier ----------
    if (t == 0) {
        atomicAdd(&g_acc.counter, 1u);
        volatile unsigned int* ctr = &g_acc.counter;
        while (*ctr < gridDim.x) {
            __nanosleep(64);
        }
        __threadfence();
    }
    __syncthreads();

    if (t < C) {
        s_mean[t] = g_acc.sum[t] / fmaxf(g_acc.cnt[t], 1.0f);
    }
    __syncthreads();

    // ---------- phase 2: scatter-fix NaN lanes only ----------
    unsigned long long any = m0 | m1 | m2 | m3;
    if (any) {
        const float mu0 = s_mean[cbase + 0];
        const float mu1 = s_mean[cbase + 1];
        const float mu2 = s_mean[cbase + 2];
        const float mu3 = s_mean[cbase + 3];
        float* outf = (float*)out;
        while (any) {
            int k = __ffsll((long long)any) - 1;
            any &= any - 1ull;
            long long e = (start + (long long)k * THREADS) * 4;  // float index
            unsigned long long bit = 1ull << k;
            if (m0 & bit) outf[e + 0] = mu0;
            if (m1 & bit) outf[e + 1] = mu1;
            if (m2 & bit) outf[e + 2] = mu2;
            if (m3 & bit) outf[e + 3] = mu3;
        }
    }
}

extern "C" void kernel_launch(void* const* d_in, const int* in_sizes, int n_in,
                              void* d_out, int out_size) {
    const float4* in = (const float4*)d_in[0];
    float4* out      = (float4*)d_out;
    long long n  = (long long)in_sizes[0];
    long long n4 = n / 4;

    static int grid = 0;
    static void* acc_ptr = nullptr;
    if (grid == 0) {
        int sm_count = 0;
        cudaDeviceGetAttribute(&sm_count, cudaDevAttrMultiProcessorCount, 0);
        int blocks_per_sm = 0;
        cudaOccupancyMaxActiveBlocksPerMultiprocessor(
            &blocks_per_sm, fused_kernel, THREADS, 0);
        if (blocks_per_sm < 1) blocks_per_sm = 1;
        grid = sm_count * blocks_per_sm;
        cudaGetSymbolAddress(&acc_ptr, g_acc);
    }

    long long chunk = (n4 + grid - 1) / grid;
    // Each thread must fit its iteration count in a 64-bit mask.
    // iters_per_thread = ceil(chunk / THREADS); shrink grid never, chunk is
    // n4/grid ~ 8772 -> 35 iters with grid≈912; safe up to 64*256=16384.

    cudaMemsetAsync(acc_ptr, 0, sizeof(Acc));
    fused_kernel<<<grid, THREADS>>>(in, out, n4, chunk);
}